// round 3
// baseline (speedup 1.0000x reference)
#include <cuda_runtime.h>
#include <math.h>

// ---------------------------------------------------------------------------
// Scratch (no allocs allowed -> __device__ globals)
// ---------------------------------------------------------------------------
__device__ float g_bufA[4096 * 2048];
__device__ float g_bufB[4096 * 2048];

// ---------------------------------------------------------------------------
// SGEMM: C[M,N] = A[M,K] @ B[K,N] + bias[N]   (all row-major, fp32)
// 128x128 block tile, BK=8, 8x8 per thread, 256 threads.
// M % 128 == 0 and K % 8 == 0 are guaranteed by the launch shapes.
// N may be ragged (N=1000) -> guarded loads/stores on the N edge.
// ---------------------------------------------------------------------------
constexpr int BM = 128, BN = 128, BK = 8, TM = 8, TN = 8;

__global__ __launch_bounds__(256) void sgemm_bias(
    int M, int N, int K,
    const float* __restrict__ A, const float* __restrict__ B,
    const float* __restrict__ bias, float* __restrict__ C)
{
    __shared__ __align__(16) float As[BK][BM];
    __shared__ __align__(16) float Bs[BK][BN];

    const int tid = threadIdx.x;
    const int bm  = blockIdx.y * BM;
    const int bn  = blockIdx.x * BN;
    const int ty  = tid / (BN / TN);   // 0..15
    const int tx  = tid % (BN / TN);   // 0..15

    float acc[TM][TN];
    #pragma unroll
    for (int i = 0; i < TM; i++)
        #pragma unroll
        for (int j = 0; j < TN; j++)
            acc[i][j] = 0.0f;

    // Loader assignments: each thread loads one float4 of A and one of B
    const int am  = tid >> 1;           // 0..127
    const int ak  = (tid & 1) * 4;      // 0 or 4
    const int bk  = tid >> 5;           // 0..7
    const int bn4 = (tid & 31) * 4;     // 0..124

    for (int k0 = 0; k0 < K; k0 += BK) {
        // A tile (K divisible by 4 in all call sites -> aligned float4)
        float4 av = *reinterpret_cast<const float4*>(
            &A[(size_t)(bm + am) * K + k0 + ak]);
        As[ak + 0][am] = av.x;
        As[ak + 1][am] = av.y;
        As[ak + 2][am] = av.z;
        As[ak + 3][am] = av.w;

        // B tile (guard the N edge)
        int col = bn + bn4;
        if (col + 3 < N) {
            float4 bv = *reinterpret_cast<const float4*>(
                &B[(size_t)(k0 + bk) * N + col]);
            Bs[bk][bn4 + 0] = bv.x;
            Bs[bk][bn4 + 1] = bv.y;
            Bs[bk][bn4 + 2] = bv.z;
            Bs[bk][bn4 + 3] = bv.w;
        } else {
            #pragma unroll
            for (int e = 0; e < 4; e++)
                Bs[bk][bn4 + e] = (col + e < N)
                    ? B[(size_t)(k0 + bk) * N + col + e] : 0.0f;
        }
        __syncthreads();

        #pragma unroll
        for (int kk = 0; kk < BK; kk++) {
            float4 a0 = *reinterpret_cast<const float4*>(&As[kk][ty * TM]);
            float4 a1 = *reinterpret_cast<const float4*>(&As[kk][ty * TM + 4]);
            float4 b0 = *reinterpret_cast<const float4*>(&Bs[kk][tx * TN]);
            float4 b1 = *reinterpret_cast<const float4*>(&Bs[kk][tx * TN + 4]);
            float ra[TM] = {a0.x, a0.y, a0.z, a0.w, a1.x, a1.y, a1.z, a1.w};
            float rb[TN] = {b0.x, b0.y, b0.z, b0.w, b1.x, b1.y, b1.z, b1.w};
            #pragma unroll
            for (int i = 0; i < TM; i++)
                #pragma unroll
                for (int j = 0; j < TN; j++)
                    acc[i][j] += ra[i] * rb[j];
        }
        __syncthreads();
    }

    #pragma unroll
    for (int i = 0; i < TM; i++) {
        int rowc = bm + ty * TM + i;
        #pragma unroll
        for (int j = 0; j < TN; j++) {
            int col = bn + tx * TN + j;
            if (col < N)
                C[(size_t)rowc * N + col] = acc[i][j] + bias[col];
        }
    }
}

// ---------------------------------------------------------------------------
// Quantum circuit kernel: one block per batch row.
// AmplitudeEmbedding(normalize) + 3x StronglyEntanglingLayers + probs.
// wire q  <->  bit (9 - q) of the flat amplitude index (wire 0 = MSB).
// Rot(phi,theta,omega) needs only 4 scalars:
//   A = cos(a)cos(t/2), B = sin(a)cos(t/2), Cc = cos(b)sin(t/2), D = sin(b)sin(t/2)
// with a = (phi+omega)/2, b = (phi-omega)/2.
//   U00 = (A,-B)  U01 = (-Cc,-D)  U10 = (Cc,-D)  U11 = (A,B)
// ---------------------------------------------------------------------------
__global__ __launch_bounds__(256) void circuit_kernel(
    const float* __restrict__ x,    // [4096, 1024]
    const float* __restrict__ w,    // [3, 10, 3]
    float* __restrict__ out)        // [4096, 1024] probs
{
    __shared__ float sre[1024];
    __shared__ float sim[1024];
    __shared__ float Ug[30][4];
    __shared__ float red[8];

    const int row = blockIdx.x;
    const int tid = threadIdx.x;

    // Precompute all 30 gate matrices (threads 0..29)
    if (tid < 30) {
        float phi = w[tid * 3 + 0];
        float th  = w[tid * 3 + 1];
        float om  = w[tid * 3 + 2];
        float s, c;   sincosf(0.5f * th, &s, &c);
        float sa, ca; sincosf(0.5f * (phi + om), &sa, &ca);
        float sb, cb; sincosf(0.5f * (phi - om), &sb, &cb);
        Ug[tid][0] = ca * c;  // A
        Ug[tid][1] = sa * c;  // B
        Ug[tid][2] = cb * s;  // Cc
        Ug[tid][3] = sb * s;  // D
    }

    // Load row, compute L2 norm, write normalized state into smem
    float v[4];
    float ss = 0.0f;
    #pragma unroll
    for (int j = 0; j < 4; j++) {
        v[j] = x[(size_t)row * 1024 + tid + j * 256];
        ss += v[j] * v[j];
    }
    #pragma unroll
    for (int o = 16; o > 0; o >>= 1)
        ss += __shfl_xor_sync(0xFFFFFFFFu, ss, o);
    if ((tid & 31) == 0) red[tid >> 5] = ss;
    __syncthreads();
    float tot = 0.0f;
    #pragma unroll
    for (int j = 0; j < 8; j++) tot += red[j];
    float inv = rsqrtf(tot);
    #pragma unroll
    for (int j = 0; j < 4; j++) {
        sre[tid + j * 256] = v[j] * inv;
        sim[tid + j * 256] = 0.0f;
    }
    __syncthreads();

    for (int l = 0; l < 3; l++) {
        // --- single-qubit rotations ---
        for (int q = 0; q < 10; q++) {
            const int g = l * 10 + q;
            const float Am = Ug[g][0], Bm = Ug[g][1];
            const float Cm = Ug[g][2], Dm = Ug[g][3];
            const int bit = 9 - q;
            const int mask = 1 << bit;
            #pragma unroll
            for (int p = tid; p < 512; p += 256) {
                int lo = p & (mask - 1);
                int i0 = ((p - lo) << 1) | lo;
                int i1 = i0 | mask;
                float a0r = sre[i0], a0i = sim[i0];
                float a1r = sre[i1], a1i = sim[i1];
                sre[i0] = Am * a0r + Bm * a0i - Cm * a1r + Dm * a1i;
                sim[i0] = Am * a0i - Bm * a0r - Cm * a1i - Dm * a1r;
                sre[i1] = Cm * a0r + Dm * a0i + Am * a1r - Bm * a1i;
                sim[i1] = Cm * a0i - Dm * a0r + Am * a1i + Bm * a1r;
            }
            __syncthreads();
        }
        // --- CNOT ring, range r = l % 9 + 1 (sequential, non-commuting) ---
        const int r = l % 9 + 1;
        for (int q = 0; q < 10; q++) {
            const int cb = 9 - q;
            const int tb = 9 - ((q + r) % 10);
            const int cmask = 1 << cb;
            const int tmask = 1 << tb;
            const int b1 = cb < tb ? cb : tb;
            const int b2 = cb < tb ? tb : cb;
            // 256 indices with control=1, target=0 : one swap per thread
            int p  = tid;
            int lo = p & ((1 << b1) - 1);
            int mid = (p >> b1) & ((1 << (b2 - b1 - 1)) - 1);
            int hi = p >> (b2 - 1);
            int idx = (hi << (b2 + 1)) | (mid << (b1 + 1)) | lo | cmask;
            int j2 = idx | tmask;
            float tr = sre[idx], ti = sim[idx];
            sre[idx] = sre[j2]; sim[idx] = sim[j2];
            sre[j2] = tr;       sim[j2] = ti;
            __syncthreads();
        }
    }

    // probs
    #pragma unroll
    for (int j = 0; j < 4; j++) {
        int i = tid + j * 256;
        out[(size_t)row * 1024 + i] = sre[i] * sre[i] + sim[i] * sim[i];
    }
}

// ---------------------------------------------------------------------------
// Final: y = |x| ; y /= rowsum(y)        x: [4096, 1000]
// ---------------------------------------------------------------------------
__global__ __launch_bounds__(256) void abs_norm_kernel(
    const float* __restrict__ x, float* __restrict__ out)
{
    __shared__ float red[8];
    const int row = blockIdx.x;
    const int tid = threadIdx.x;

    float v[4];
    float ss = 0.0f;
    #pragma unroll
    for (int j = 0; j < 4; j++) {
        int i = tid + j * 256;
        v[j] = (i < 1000) ? fabsf(x[(size_t)row * 1000 + i]) : 0.0f;
        ss += v[j];
    }
    #pragma unroll
    for (int o = 16; o > 0; o >>= 1)
        ss += __shfl_xor_sync(0xFFFFFFFFu, ss, o);
    if ((tid & 31) == 0) red[tid >> 5] = ss;
    __syncthreads();
    float tot = 0.0f;
    #pragma unroll
    for (int j = 0; j < 8; j++) tot += red[j];
    float inv = 1.0f / tot;
    #pragma unroll
    for (int j = 0; j < 4; j++) {
        int i = tid + j * 256;
        if (i < 1000)
            out[(size_t)row * 1000 + i] = v[j] * inv;
    }
}

// ---------------------------------------------------------------------------
// Launch
// ---------------------------------------------------------------------------
extern "C" void kernel_launch(void* const* d_in, const int* in_sizes, int n_in,
                              void* d_out, int out_size)
{
    const float* inputs = (const float*)d_in[0];
    const float* wEnc   = (const float*)d_in[1];
    const float* wDec   = (const float*)d_in[2];
    const float* W0     = (const float*)d_in[3];
    const float* b0     = (const float*)d_in[4];
    const float* W1     = (const float*)d_in[5];
    const float* b1     = (const float*)d_in[6];
    const float* W2     = (const float*)d_in[7];
    const float* b2     = (const float*)d_in[8];
    const float* W3     = (const float*)d_in[9];
    const float* b3     = (const float*)d_in[10];
    float* outp = (float*)d_out;

    float *bufA = nullptr, *bufB = nullptr;
    cudaGetSymbolAddress((void**)&bufA, g_bufA);
    cudaGetSymbolAddress((void**)&bufB, g_bufB);

    dim3 blk(256);

    // x = inputs @ W0 + b0                      [4096,1024]
    sgemm_bias<<<dim3(8, 32), blk>>>(4096, 1024, 1000, inputs, W0, b0, bufA);
    // x = circuit(x, wEnc)                      [4096,1024]
    circuit_kernel<<<4096, blk>>>(bufA, wEnc, bufB);
    // x = x @ W1 + b1                           [4096,2048]
    sgemm_bias<<<dim3(16, 32), blk>>>(4096, 2048, 1024, bufB, W1, b1, bufA);
    // x = x @ W2 + b2                           [4096,1024]
    sgemm_bias<<<dim3(8, 32), blk>>>(4096, 1024, 2048, bufA, W2, b2, bufB);
    // x = circuit(x, wDec)                      [4096,1024]
    circuit_kernel<<<4096, blk>>>(bufB, wDec, bufA);
    // x = x @ W3 + b3                           [4096,1000]
    sgemm_bias<<<dim3(8, 32), blk>>>(4096, 1000, 1024, bufA, W3, b3, bufB);
    // out = |x| / rowsum(|x|)
    abs_norm_kernel<<<4096, blk>>>(bufB, outp);
}